// round 6
// baseline (speedup 1.0000x reference)
#include <cuda_runtime.h>
#include <math.h>

// Problem constants
#define B_    64
#define NN_   236
#define C_    768
#define H_    8
#define D_    96
#define S1_   196
#define S2_   216
#define BIAS_ 100.0f
#define M_TOT (B_*NN_)     // 15104
#define QKV_N (3*C_)       // 2304
#define KLD   97           // padded K leading dim in smem (conflict-free)

typedef unsigned long long u64;

// Packed fp32x2 FMA (Blackwell sm_103a, exact fp32 semantics, 2x throughput)
#define FMA2(acc, a, b) \
    asm("fma.rn.f32x2 %0, %1, %2, %0;" : "+l"(acc) : "l"(a), "l"(b))
#define DUP2(out, v) \
    asm("mov.b64 %0, {%1, %1};" : "=l"(out) : "f"(v))
#define PACK2(out, lo, hi) \
    asm("mov.b64 %0, {%1, %2};" : "=l"(out) : "f"(lo), "f"(hi))
#define UNPK2(lo, hi, in) \
    asm("mov.b64 {%0, %1}, %2;" : "=f"(lo), "=f"(hi) : "l"(in))

// Scratch (alloc-free rule: __device__ globals)
__device__ float g_qkv[(size_t)3*B_*H_*NN_*D_];   // [3][B][H][N][D]
__device__ float g_attn[(size_t)M_TOT*C_];        // [B*N][C]

// ---------------------------------------------------------------------------
// Tiled fp32 GEMM: C[M,N] = A[M,K] * W[N,K]^T   (both row-major, K=768)
// 128x128 tile, 256 threads, 8x8 per thread, BK=16.
// Register-prefetch pipelined; inner product via packed fma.rn.f32x2.
// ---------------------------------------------------------------------------
__global__ __launch_bounds__(256) void gemm_qkv(const float* __restrict__ X,
                                                const float* __restrict__ W) {
    __shared__ float As[16][132];
    __shared__ float Bs[16][132];
    const int m0 = blockIdx.y * 128;
    const int n0 = blockIdx.x * 128;
    const int tid = threadIdx.x;
    const int tx = tid & 15, ty = tid >> 4;

    int lrow[2], lkc[2];
    #pragma unroll
    for (int i = 0; i < 2; i++) {
        int li = tid + i * 256;
        lrow[i] = li >> 2;
        lkc[i]  = (li & 3) << 2;
    }

    u64 acc2[8][4];
    #pragma unroll
    for (int i = 0; i < 8; i++)
        #pragma unroll
        for (int j = 0; j < 4; j++) acc2[i][j] = 0ull;   // (0.f, 0.f)

    // prefetch kt = 0
    float4 pa[2], pb[2];
    #pragma unroll
    for (int i = 0; i < 2; i++) {
        pa[i] = *(const float4*)(X + (size_t)(m0 + lrow[i]) * C_ + lkc[i]);
        pb[i] = *(const float4*)(W + (size_t)(n0 + lrow[i]) * C_ + lkc[i]);
    }

    for (int kt = 0; kt < C_; kt += 16) {
        #pragma unroll
        for (int i = 0; i < 2; i++) {
            int row = lrow[i], kc = lkc[i];
            As[kc+0][row] = pa[i].x; As[kc+1][row] = pa[i].y;
            As[kc+2][row] = pa[i].z; As[kc+3][row] = pa[i].w;
            Bs[kc+0][row] = pb[i].x; Bs[kc+1][row] = pb[i].y;
            Bs[kc+2][row] = pb[i].z; Bs[kc+3][row] = pb[i].w;
        }
        __syncthreads();

        int ktn = kt + 16;
        if (ktn < C_) {
            #pragma unroll
            for (int i = 0; i < 2; i++) {
                pa[i] = *(const float4*)(X + (size_t)(m0 + lrow[i]) * C_ + ktn + lkc[i]);
                pb[i] = *(const float4*)(W + (size_t)(n0 + lrow[i]) * C_ + ktn + lkc[i]);
            }
        }

        #pragma unroll
        for (int k = 0; k < 16; k++) {
            u64 a2[8], b2[4];
            #pragma unroll
            for (int i = 0; i < 8; i++)
                DUP2(a2[i], As[k][ty*8 + i]);
            #pragma unroll
            for (int j = 0; j < 4; j++)
                b2[j] = *(const u64*)&Bs[k][tx*8 + 2*j];   // 8B-aligned
            #pragma unroll
            for (int i = 0; i < 8; i++)
                #pragma unroll
                for (int j = 0; j < 4; j++)
                    FMA2(acc2[i][j], a2[i], b2[j]);
        }
        __syncthreads();
    }

    // Scatter into [3][B][H][N][D]  (c' = which*768 + h*96 + d)
    #pragma unroll
    for (int i = 0; i < 8; i++) {
        int row = m0 + ty*8 + i;
        int b = row / NN_;
        int n = row - b * NN_;
        #pragma unroll
        for (int j = 0; j < 4; j++) {
            float lo, hi;
            UNPK2(lo, hi, acc2[i][j]);
            #pragma unroll
            for (int s = 0; s < 2; s++) {
                int col = n0 + tx*8 + 2*j + s;
                float v = s ? hi : lo;
                int which = col / C_;
                int rem = col - which * C_;
                int h  = rem / D_;
                int dd = rem - h * D_;
                g_qkv[(((size_t)which * (B_*H_) + b*H_ + h) * NN_ + n) * D_ + dd] = v;
            }
        }
    }
}

__global__ __launch_bounds__(256) void gemm_proj(const float* __restrict__ W,
                                                 const float* __restrict__ bias,
                                                 float* __restrict__ out) {
    __shared__ float As[16][132];
    __shared__ float Bs[16][132];
    const int m0 = blockIdx.y * 128;
    const int n0 = blockIdx.x * 128;
    const int tid = threadIdx.x;
    const int tx = tid & 15, ty = tid >> 4;

    int lrow[2], lkc[2];
    #pragma unroll
    for (int i = 0; i < 2; i++) {
        int li = tid + i * 256;
        lrow[i] = li >> 2;
        lkc[i]  = (li & 3) << 2;
    }

    u64 acc2[8][4];
    #pragma unroll
    for (int i = 0; i < 8; i++)
        #pragma unroll
        for (int j = 0; j < 4; j++) acc2[i][j] = 0ull;

    float4 pa[2], pb[2];
    #pragma unroll
    for (int i = 0; i < 2; i++) {
        pa[i] = *(const float4*)(g_attn + (size_t)(m0 + lrow[i]) * C_ + lkc[i]);
        pb[i] = *(const float4*)(W + (size_t)(n0 + lrow[i]) * C_ + lkc[i]);
    }

    for (int kt = 0; kt < C_; kt += 16) {
        #pragma unroll
        for (int i = 0; i < 2; i++) {
            int row = lrow[i], kc = lkc[i];
            As[kc+0][row] = pa[i].x; As[kc+1][row] = pa[i].y;
            As[kc+2][row] = pa[i].z; As[kc+3][row] = pa[i].w;
            Bs[kc+0][row] = pb[i].x; Bs[kc+1][row] = pb[i].y;
            Bs[kc+2][row] = pb[i].z; Bs[kc+3][row] = pb[i].w;
        }
        __syncthreads();

        int ktn = kt + 16;
        if (ktn < C_) {
            #pragma unroll
            for (int i = 0; i < 2; i++) {
                pa[i] = *(const float4*)(g_attn + (size_t)(m0 + lrow[i]) * C_ + ktn + lkc[i]);
                pb[i] = *(const float4*)(W + (size_t)(n0 + lrow[i]) * C_ + ktn + lkc[i]);
            }
        }

        #pragma unroll
        for (int k = 0; k < 16; k++) {
            u64 a2[8], b2[4];
            #pragma unroll
            for (int i = 0; i < 8; i++)
                DUP2(a2[i], As[k][ty*8 + i]);
            #pragma unroll
            for (int j = 0; j < 4; j++)
                b2[j] = *(const u64*)&Bs[k][tx*8 + 2*j];
            #pragma unroll
            for (int i = 0; i < 8; i++)
                #pragma unroll
                for (int j = 0; j < 4; j++)
                    FMA2(acc2[i][j], a2[i], b2[j]);
        }
        __syncthreads();
    }

    #pragma unroll
    for (int i = 0; i < 8; i++) {
        int row = m0 + ty*8 + i;
        #pragma unroll
        for (int j = 0; j < 4; j++) {
            float lo, hi;
            UNPK2(lo, hi, acc2[i][j]);
            int col = n0 + tx*8 + 2*j;
            out[(size_t)row * C_ + col]     = lo + bias[col];
            out[(size_t)row * C_ + col + 1] = hi + bias[col + 1];
        }
    }
}

// ---------------------------------------------------------------------------
// Attention: one CTA per (b,h). K,V staged in smem. 8 warps x 4 rows/warp.
// QK^T loop uses packed fma.rn.f32x2 over row-pairs (exact fp32).
// smem: Ksh[256][97] | Vsh[236*96] | scratch[8 warps][960]
// ---------------------------------------------------------------------------
#define ATTN_SMEM_FLOATS (256*KLD + NN_*D_ + 8*960)
#define ATTN_SMEM_BYTES  (ATTN_SMEM_FLOATS * 4)

__global__ __launch_bounds__(256) void attn_kernel() {
    extern __shared__ float smem[];
    float* Ksh = smem;                    // 256*97
    float* Vsh = smem + 256*KLD;          // 236*96
    float* scr = Vsh + NN_*D_;            // 8*960

    const int bx = blockIdx.x;            // b*8 + h
    const float* Qg = g_qkv + (size_t)bx * NN_ * D_;
    const float* Kg = g_qkv + ((size_t)(B_*H_) + bx) * NN_ * D_;
    const float* Vg = g_qkv + ((size_t)(2*B_*H_) + bx) * NN_ * D_;

    const int tid = threadIdx.x;
    const int w = tid >> 5, lane = tid & 31;

    // Stage K (padded ld=97, vectorized global reads) and V (ld=96)
    for (int i = tid; i < (NN_*D_)/4; i += 256) {
        float4 kv = ((const float4*)Kg)[i];
        int e = i * 4;
        int r = e / D_, c = e - r*D_;     // D_%4==0 so 4 elems stay in-row
        float* dst = Ksh + r*KLD + c;
        dst[0] = kv.x; dst[1] = kv.y; dst[2] = kv.z; dst[3] = kv.w;
    }
    for (int i = tid; i < (NN_*D_)/4; i += 256)
        ((float4*)Vsh)[i] = ((const float4*)Vg)[i];
    // zero K pad rows 236..255 so the guard-free inner loop reads zeros
    for (int i = tid; i < (256-NN_)*D_; i += 256) {
        int r = NN_ + i / D_, c = i % D_;
        Ksh[r*KLD + c] = 0.f;
    }
    __syncthreads();

    const float scale = rsqrtf((float)D_);
    float* ws = scr + w * 960;            // per-warp scratch: 4 rows x 240

    for (int iter = 0; iter < 8; iter++) {
        int n0 = iter * 32 + w * 4;
        if (n0 >= NN_) continue;          // only __syncwarp below; safe

        // load 4 q rows into ws[r*240 + d] (vectorized: both sides 16B-aligned)
        for (int t = lane; t < 4*(D_/4); t += 32) {
            int r = t / (D_/4), d4 = t - r*(D_/4);
            float4 qv = *(const float4*)(Qg + (size_t)(n0 + r) * D_ + 4*d4);
            *(float4*)(ws + r*240 + 4*d4) = qv;
        }
        __syncwarp();

        // scores: lane owns columns m = j*32 + lane.
        // Row pairs (0,1),(2,3) packed into f32x2 accumulators.
        u64 acc01[8], acc23[8];
        #pragma unroll
        for (int j = 0; j < 8; j++) { acc01[j] = 0ull; acc23[j] = 0ull; }

        for (int d = 0; d < D_; d++) {
            u64 q01, q23;
            PACK2(q01, ws[d],     ws[240+d]);
            PACK2(q23, ws[480+d], ws[720+d]);
            #pragma unroll
            for (int j = 0; j < 8; j++) {
                u64 kv2;
                DUP2(kv2, Ksh[(j*32 + lane)*KLD + d]);
                FMA2(acc01[j], q01, kv2);
                FMA2(acc23[j], q23, kv2);
            }
        }
        __syncwarp();   // everyone done reading q before we overwrite ws

        #pragma unroll
        for (int j = 0; j < 8; j++) {
            int m = j*32 + lane;
            if (m < NN_) {
                float s0, s1, s2, s3;
                UNPK2(s0, s1, acc01[j]);
                UNPK2(s2, s3, acc23[j]);
                ws[m]       = s0 * scale;
                ws[240 + m] = s1 * scale;
                ws[480 + m] = s2 * scale;
                ws[720 + m] = s3 * scale;
            }
        }
        __syncwarp();

        // block edits + softmax per row
        float inv[4];
        #pragma unroll
        for (int r = 0; r < 4; r++) {
            int n = n0 + r;
            float* srow = ws + r*240;
            if (lane < (S2_ - S1_)) {     // 20 lanes
                if (n < S1_) {
                    // copy uses PRE-bias values, then bias the source block
                    float t = srow[S1_ + lane];
                    srow[S2_ + lane] = t;
                    srow[S1_ + lane] = t - BIAS_;
                } else if (n < S2_) {
                    srow[S2_ + lane] -= BIAS_;
                } else {
                    srow[S1_ + lane] -= BIAS_;
                }
            }
            __syncwarp();
            float mx = -1e30f;
            #pragma unroll
            for (int j = 0; j < 8; j++) {
                int m = j*32 + lane;
                if (m < NN_) mx = fmaxf(mx, srow[m]);
            }
            #pragma unroll
            for (int o = 16; o > 0; o >>= 1)
                mx = fmaxf(mx, __shfl_xor_sync(0xffffffffu, mx, o));
            float sum = 0.f;
            #pragma unroll
            for (int j = 0; j < 8; j++) {
                int m = j*32 + lane;
                if (m < NN_) {
                    float e = __expf(srow[m] - mx);
                    srow[m] = e;
                    sum += e;
                }
            }
            #pragma unroll
            for (int o = 16; o > 0; o >>= 1)
                sum += __shfl_xor_sync(0xffffffffu, sum, o);
            inv[r] = 1.f / sum;
            __syncwarp();
        }

        // out = P @ V : lane owns d = lane, lane+32, lane+64
        float o0[4], o1[4], o2[4];
        #pragma unroll
        for (int r = 0; r < 4; r++) { o0[r]=0.f; o1[r]=0.f; o2[r]=0.f; }
        for (int m = 0; m < NN_; m++) {
            float v0 = Vsh[m*D_ + lane];
            float v1 = Vsh[m*D_ + lane + 32];
            float v2 = Vsh[m*D_ + lane + 64];
            #pragma unroll
            for (int r = 0; r < 4; r++) {
                float p = ws[r*240 + m];
                o0[r] = fmaf(p, v0, o0[r]);
                o1[r] = fmaf(p, v1, o1[r]);
                o2[r] = fmaf(p, v2, o2[r]);
            }
        }
        int b = bx >> 3, h = bx & 7;
        #pragma unroll
        for (int r = 0; r < 4; r++) {
            size_t base = ((size_t)(b*NN_ + n0 + r)) * C_ + h*D_;
            g_attn[base + lane]      = o0[r] * inv[r];
            g_attn[base + lane + 32] = o1[r] * inv[r];
            g_attn[base + lane + 64] = o2[r] * inv[r];
        }
        __syncwarp();   // ws reads done before next iter overwrites q
    }
}

// ---------------------------------------------------------------------------
extern "C" void kernel_launch(void* const* d_in, const int* in_sizes, int n_in,
                              void* d_out, int out_size) {
    const float* x      = (const float*)d_in[0];
    const float* qkv_w  = (const float*)d_in[1];
    const float* proj_w = (const float*)d_in[2];
    const float* proj_b = (const float*)d_in[3];
    float* out = (float*)d_out;

    gemm_qkv<<<dim3(QKV_N/128, M_TOT/128), 256>>>(x, qkv_w);

    cudaFuncSetAttribute(attn_kernel,
                         cudaFuncAttributeMaxDynamicSharedMemorySize,
                         ATTN_SMEM_BYTES);
    attn_kernel<<<B_*H_, 256, ATTN_SMEM_BYTES>>>();

    gemm_proj<<<dim3(C_/128, M_TOT/128), 256>>>(proj_w, proj_b, out);
}